// round 9
// baseline (speedup 1.0000x reference)
#include <cuda_runtime.h>
#include <cuda_fp16.h>
#include <cstdint>

#define NNODES 4096
#define RREL   16
#define NBASES 8
#define DIN    64
#define DOUT   32
#define KFULL  (RREL * NNODES)          // 65536

#define M_TILE 128
#define KT     64                       // k per step (4 mma k-tiles of 16)
#define KSPLIT 64
#define KCHUNK (KFULL / KSPLIT)         // 1024
#define NSTEPS (KCHUNK / KT)            // 16

// per-stage smem layout (bytes): A 16K | B-hi 4K | B-lo 4K
#define OFF_AH 0
#define OFF_BH 16384
#define OFF_BL 20480
#define STG_B  24576
#define SMEM_BYTES (2 * STG_B)          // 48 KB dynamic

__device__ float g_W[RREL * DIN * DOUT];
__device__ __half g_Bh[(size_t)DOUT * KFULL];            // [c][k], 4 MB
__device__ __half g_Bl[(size_t)DOUT * KFULL];            // 4 MB
__device__ float g_part[(size_t)KSPLIT * NNODES * DOUT]; // 32 MB

__device__ __forceinline__ void mma16816(float* d, const uint32_t* a,
                                         uint32_t b0, uint32_t b1) {
    asm volatile(
        "mma.sync.aligned.m16n8k16.row.col.f32.f16.f16.f32 "
        "{%0,%1,%2,%3}, {%4,%5,%6,%7}, {%8,%9}, {%0,%1,%2,%3};"
        : "+f"(d[0]), "+f"(d[1]), "+f"(d[2]), "+f"(d[3])
        : "r"(a[0]), "r"(a[1]), "r"(a[2]), "r"(a[3]), "r"(b0), "r"(b1));
}
__device__ __forceinline__ void cp_async16(uint32_t saddr, const void* g) {
    asm volatile("cp.async.cg.shared.global [%0], [%1], 16;" :: "r"(saddr), "l"(g));
}
__device__ __forceinline__ void ldmatrix_x4(uint32_t* r, uint32_t addr) {
    asm volatile("ldmatrix.sync.aligned.m8n8.x4.shared.b16 {%0,%1,%2,%3}, [%4];"
                 : "=r"(r[0]), "=r"(r[1]), "=r"(r[2]), "=r"(r[3]) : "r"(addr));
}
// evict-first streaming load of a float4 (A is single-use; keep B hot in L2)
__device__ __forceinline__ float4 ldcs4(const float* p) {
    float4 v;
    asm volatile("ld.global.cs.v4.f32 {%0,%1,%2,%3}, [%4];"
                 : "=f"(v.x), "=f"(v.y), "=f"(v.z), "=f"(v.w) : "l"(p));
    return v;
}

// Stage 1: W[r,i,j] = sum_b comp[r,b] * WF[b,i,j]
__global__ void k_basis(const float* __restrict__ WF, const float* __restrict__ comp) {
    int idx = blockIdx.x * blockDim.x + threadIdx.x;
    if (idx >= RREL * DIN * DOUT) return;
    int r = idx / (DIN * DOUT), ij = idx % (DIN * DOUT);
    float s = 0.f;
#pragma unroll
    for (int b = 0; b < NBASES; ++b)
        s += comp[r * NBASES + b] * WF[b * (DIN * DOUT) + ij];
    g_W[idx] = s;
}

// Stage 2: FW = X @ W_r -> fp16 hi/lo split, transposed [c][k]
__global__ void k_fw(const float* __restrict__ X) {
    __shared__ float Ws[DIN * DOUT];
    __shared__ float Xs[32 * DIN];
    const int r = blockIdx.x, nblk = blockIdx.y, t = threadIdx.x;

    for (int i = t; i < DIN * DOUT; i += 256) Ws[i] = g_W[r * DIN * DOUT + i];
    for (int i = t; i < 32 * DIN;  i += 256) Xs[i] = X[(size_t)(nblk * 32) * DIN + i];
    __syncthreads();

    const int row = t >> 3;
    const int c0  = (t & 7) * 4;
    float a[4] = {0.f, 0.f, 0.f, 0.f};
#pragma unroll
    for (int i = 0; i < DIN; ++i) {
        float x = Xs[row * DIN + i];
        float4 w = *(const float4*)&Ws[i * DOUT + c0];
        a[0] += x * w.x; a[1] += x * w.y; a[2] += x * w.z; a[3] += x * w.w;
    }
    int k = r * NNODES + nblk * 32 + row;
#pragma unroll
    for (int i = 0; i < 4; ++i) {
        __half h = __float2half_rn(a[i]);
        __half l = __float2half_rn(a[i] - __half2float(h));
        g_Bh[(size_t)(c0 + i) * KFULL + k] = h;
        g_Bl[(size_t)(c0 + i) * KFULL + k] = l;
    }
}

// Stage 3: split-K GEMM. Streaming fp32 LDG.cs -> in-reg fp16 convert ->
// SW128-swizzled smem -> ldmatrix x4 fragments -> 2-product mma (A*(Bh+Bl)).
// Warp tiling 4x2: warp = 32 rows x 16 cols (min fragment traffic).
__global__ __launch_bounds__(256, 2) void k_gemm(const float* __restrict__ A) {
    extern __shared__ char smem[];
    const uint32_t sbase = (uint32_t)__cvta_generic_to_shared(smem);

    const int t    = threadIdx.x;
    const int wid  = t >> 5, lane = t & 31;
    const int m0   = blockIdx.x * M_TILE;
    const size_t kb0 = (size_t)blockIdx.y * KCHUNK;

    // warp tile coordinates: 4 row-groups x 2 n-groups
    const int wr = wid >> 1;            // row group: rows wr*32 .. wr*32+31
    const int wn = wid & 1;             // n group: cols wn*16 .. wn*16+15

    // A loader mapping: rows arow0 + 16*i, float4 position apos
    const int arow0 = t >> 4;
    const int apos  = t & 15;
    const float* Asrc = A + (size_t)m0 * KFULL + kb0 + apos * 4;

    // B loader mapping (cp.async, swizzled dst)
    const int bn = t >> 3, bkc = t & 7;
    const uint32_t boff = bn * 128 + ((bkc ^ (bn & 7)) << 4);
    const __half* bsrc_h = g_Bh + (size_t)bn * KFULL + kb0 + bkc * 8;
    const __half* bsrc_l = g_Bl + (size_t)bn * KFULL + kb0 + bkc * 8;

    // ldmatrix per-lane patterns
    const int a_row  = wr * 32 + (lane & 15);           // rt=0 row; rt=1 adds 16
    const int a_csel = lane >> 4;
    const int bg     = lane >> 3;                       // B x4 lane group 0..3
    const int b_nrow = wn * 16 + ((bg >> 1) << 3) + (lane & 7);
    const int b_csel = bg & 1;

    // prologue: B(0) cp.async + A(0) regs
    cp_async16(sbase + OFF_BH + boff, bsrc_h);
    cp_async16(sbase + OFF_BL + boff, bsrc_l);
    asm volatile("cp.async.commit_group;");

    float4 areg[8];
#pragma unroll
    for (int i = 0; i < 8; ++i)
        areg[i] = ldcs4(Asrc + (size_t)(arow0 + 16 * i) * KFULL);

    float d[2][2][4] = {};

    for (int step = 0; step < NSTEPS; ++step) {
        const int buf = step & 1;
        const uint32_t sb = sbase + buf * STG_B;

        // convert + STS A(step) into buf
        {
            const int chunk = apos >> 1, half = apos & 1;
#pragma unroll
            for (int i = 0; i < 8; ++i) {
                const int row = arow0 + 16 * i;
                float4 f = areg[i];
                uint32_t h01, h23;
                asm("cvt.rn.f16x2.f32 %0, %1, %2;" : "=r"(h01) : "f"(f.y), "f"(f.x));
                asm("cvt.rn.f16x2.f32 %0, %1, %2;" : "=r"(h23) : "f"(f.w), "f"(f.z));
                const uint32_t off = row * 128 + ((chunk ^ (row & 7)) << 4) + half * 8;
                *(uint2*)(smem + buf * STG_B + OFF_AH + off) = make_uint2(h01, h23);
            }
        }

        // prefetch A(step+1) regs + B(step+1) cp.async into buf^1
        if (step + 1 < NSTEPS) {
            const float* asrc2 = Asrc + (step + 1) * KT;
#pragma unroll
            for (int i = 0; i < 8; ++i)
                areg[i] = ldcs4(asrc2 + (size_t)(arow0 + 16 * i) * KFULL);
            const uint32_t nb = sbase + (buf ^ 1) * STG_B;
            cp_async16(nb + OFF_BH + boff, bsrc_h + (step + 1) * KT);
            cp_async16(nb + OFF_BL + boff, bsrc_l + (step + 1) * KT);
            asm volatile("cp.async.commit_group;");
            asm volatile("cp.async.wait_group 1;");
        } else {
            asm volatile("cp.async.wait_group 0;");
        }
        __syncthreads();

        // compute on buf
        const uint32_t a_base0 = sb + OFF_AH + a_row * 128;
        const uint32_t a_base1 = a_base0 + 16 * 128;
        const uint32_t b_base  = sb + b_nrow * 128;     // + OFF_BH/OFF_BL below
#pragma unroll
        for (int kt = 0; kt < 4; ++kt) {
            const int achunk = (2 * kt + a_csel) ^ (lane & 7);
            const int bchunk = (2 * kt + b_csel) ^ (lane & 7);
            uint32_t a0[4], a1[4], bh4[4], bl4[4];
            ldmatrix_x4(a0, a_base0 + (achunk << 4));
            ldmatrix_x4(a1, a_base1 + (achunk << 4));
            ldmatrix_x4(bh4, b_base + OFF_BH + (bchunk << 4));
            ldmatrix_x4(bl4, b_base + OFF_BL + (bchunk << 4));
            mma16816(d[0][0], a0, bh4[0], bh4[1]);
            mma16816(d[0][0], a0, bl4[0], bl4[1]);
            mma16816(d[0][1], a0, bh4[2], bh4[3]);
            mma16816(d[0][1], a0, bl4[2], bl4[3]);
            mma16816(d[1][0], a1, bh4[0], bh4[1]);
            mma16816(d[1][0], a1, bl4[0], bl4[1]);
            mma16816(d[1][1], a1, bh4[2], bh4[3]);
            mma16816(d[1][1], a1, bl4[2], bl4[3]);
        }
        __syncthreads();
    }

    // epilogue: rows wr*32 + rt*16 + r4 (+8), cols wn*16 + nn*8 + kq
    const int r4 = lane >> 2, kq = (lane & 3) * 2;
    float* po = g_part + ((size_t)blockIdx.y * NNODES + m0 + wr * 32 + r4) * DOUT
                       + wn * 16 + kq;
#pragma unroll
    for (int rt = 0; rt < 2; ++rt)
#pragma unroll
        for (int nn = 0; nn < 2; ++nn) {
            *(float2*)(po + (size_t)(rt * 16)     * DOUT + nn * 8) =
                make_float2(d[rt][nn][0], d[rt][nn][1]);
            *(float2*)(po + (size_t)(rt * 16 + 8) * DOUT + nn * 8) =
                make_float2(d[rt][nn][2], d[rt][nn][3]);
        }
}

// Stage 4: deterministic split-K reduction (float granularity, 2x threads)
__global__ void k_reduce(float* __restrict__ out) {
    int i = blockIdx.x * blockDim.x + threadIdx.x;   // over 131072 floats
    const float* p = g_part;
    float s = p[i];
#pragma unroll
    for (int sdx = 1; sdx < KSPLIT; ++sdx)
        s += p[(size_t)sdx * (NNODES * DOUT) + i];
    out[i] = s;
}

extern "C" void kernel_launch(void* const* d_in, const int* in_sizes, int n_in,
                              void* d_out, int out_size) {
    const float* X    = (const float*)d_in[0];   // [4096, 64]
    const float* A    = (const float*)d_in[1];   // [4096, 65536]
    const float* WF   = (const float*)d_in[2];   // [8, 64, 32]
    const float* comp = (const float*)d_in[3];   // [16, 8]
    float* out = (float*)d_out;                  // [4096, 32]

    cudaFuncSetAttribute((const void*)k_gemm,
                         cudaFuncAttributeMaxDynamicSharedMemorySize, SMEM_BYTES);

    k_basis<<<(RREL * DIN * DOUT + 255) / 256, 256>>>(WF, comp);
    k_fw<<<dim3(RREL, NNODES / 32), 256>>>(X);
    k_gemm<<<dim3(NNODES / M_TILE, KSPLIT), 256, SMEM_BYTES>>>(A);
    k_reduce<<<(NNODES * DOUT) / 256, 256>>>(out);
}

// round 10
// speedup vs baseline: 1.0050x; 1.0050x over previous
#include <cuda_runtime.h>
#include <cuda_fp16.h>
#include <cstdint>

#define NNODES 4096
#define RREL   16
#define NBASES 8
#define DIN    64
#define DOUT   32
#define KFULL  (RREL * NNODES)          // 65536

#define M_TILE 128
#define KT     64                       // k per step (4 mma k-tiles of 16)
#define KSPLIT 64
#define KCHUNK (KFULL / KSPLIT)         // 1024
#define NSTEPS (KCHUNK / KT)            // 16

// smem: A f16 tiles 2 x 16KB | B 4-slot ring, each slot BH 4K + BL 4K
#define OFF_B  32768
#define B_STG  8192
#define SMEM_BYTES (32768 + 4 * B_STG)  // 64 KB dynamic

__device__ __half g_Bh[(size_t)DOUT * KFULL];            // [c][k], 4 MB
__device__ __half g_Bl[(size_t)DOUT * KFULL];            // 4 MB
__device__ __half g_part[(size_t)KSPLIT * NNODES * DOUT]; // fp16 partials, 16 MB

__device__ __forceinline__ void mma16816(float* d, const uint32_t* a,
                                         uint32_t b0, uint32_t b1) {
    asm volatile(
        "mma.sync.aligned.m16n8k16.row.col.f32.f16.f16.f32 "
        "{%0,%1,%2,%3}, {%4,%5,%6,%7}, {%8,%9}, {%0,%1,%2,%3};"
        : "+f"(d[0]), "+f"(d[1]), "+f"(d[2]), "+f"(d[3])
        : "r"(a[0]), "r"(a[1]), "r"(a[2]), "r"(a[3]), "r"(b0), "r"(b1));
}
__device__ __forceinline__ void cp_async16(uint32_t saddr, const void* g) {
    asm volatile("cp.async.cg.shared.global [%0], [%1], 16;" :: "r"(saddr), "l"(g));
}
__device__ __forceinline__ void ldmatrix_x4(uint32_t* r, uint32_t addr) {
    asm volatile("ldmatrix.sync.aligned.m8n8.x4.shared.b16 {%0,%1,%2,%3}, [%4];"
                 : "=r"(r[0]), "=r"(r[1]), "=r"(r[2]), "=r"(r[3]) : "r"(addr));
}
// evict-first streaming load (A is single-use; keep B hot in L2)
__device__ __forceinline__ float4 ldcs4(const float* p) {
    float4 v;
    asm volatile("ld.global.cs.v4.f32 {%0,%1,%2,%3}, [%4];"
                 : "=f"(v.x), "=f"(v.y), "=f"(v.z), "=f"(v.w) : "l"(p));
    return v;
}

// Stage 1+2 merged: W_r = comp[r] . WF (recomputed per block), then
// FW = X @ W_r -> fp16 hi/lo split, transposed [c][k]
__global__ void k_fw(const float* __restrict__ X, const float* __restrict__ WF,
                     const float* __restrict__ comp) {
    __shared__ float Ws[DIN * DOUT];
    __shared__ float Xs[32 * DIN];
    const int r = blockIdx.x, nblk = blockIdx.y, t = threadIdx.x;

    // W_r: 2048 entries, 8 per thread
#pragma unroll
    for (int j = 0; j < 8; ++j) {
        int ij = t + 256 * j;
        float s = 0.f;
#pragma unroll
        for (int b = 0; b < NBASES; ++b)
            s += comp[r * NBASES + b] * WF[b * (DIN * DOUT) + ij];
        Ws[ij] = s;
    }
    for (int i = t; i < 32 * DIN; i += 256)
        Xs[i] = X[(size_t)(nblk * 32) * DIN + i];
    __syncthreads();

    const int row = t >> 3;
    const int c0  = (t & 7) * 4;
    float a[4] = {0.f, 0.f, 0.f, 0.f};
#pragma unroll
    for (int i = 0; i < DIN; ++i) {
        float x = Xs[row * DIN + i];
        float4 w = *(const float4*)&Ws[i * DOUT + c0];
        a[0] += x * w.x; a[1] += x * w.y; a[2] += x * w.z; a[3] += x * w.w;
    }
    int k = r * NNODES + nblk * 32 + row;
#pragma unroll
    for (int i = 0; i < 4; ++i) {
        __half h = __float2half_rn(a[i]);
        __half l = __float2half_rn(a[i] - __half2float(h));
        g_Bh[(size_t)(c0 + i) * KFULL + k] = h;
        g_Bl[(size_t)(c0 + i) * KFULL + k] = l;
    }
}

// Stage 3: split-K GEMM. Streaming LDG.cs -> in-reg fp16 convert -> swizzled
// smem (A 2-buf, B 4-slot cp.async ring) -> ldmatrix x4 -> 2-product mma.
// One __syncthreads per step (hazards verified under 1-sync warp skew).
__global__ __launch_bounds__(256, 2) void k_gemm(const float* __restrict__ A) {
    extern __shared__ char smem[];
    const uint32_t sbase = (uint32_t)__cvta_generic_to_shared(smem);

    const int t    = threadIdx.x;
    const int wid  = t >> 5, lane = t & 31;
    const int m0   = blockIdx.x * M_TILE;
    const size_t kb0 = (size_t)blockIdx.y * KCHUNK;

    // warp tile coordinates: 4 row-groups x 2 n-groups
    const int wr = wid >> 1;
    const int wn = wid & 1;

    // A loader mapping
    const int arow0 = t >> 4;
    const int apos  = t & 15;
    const float* Asrc = A + (size_t)m0 * KFULL + kb0 + apos * 4;

    // B loader mapping (cp.async, swizzled dst)
    const int bn = t >> 3, bkc = t & 7;
    const uint32_t boff = bn * 128 + ((bkc ^ (bn & 7)) << 4);
    const __half* bsrc_h = g_Bh + (size_t)bn * KFULL + kb0 + bkc * 8;
    const __half* bsrc_l = g_Bl + (size_t)bn * KFULL + kb0 + bkc * 8;

    // ldmatrix per-lane patterns
    const int a_row  = wr * 32 + (lane & 15);
    const int a_csel = lane >> 4;
    const int bg     = lane >> 3;
    const int b_nrow = wn * 16 + ((bg >> 1) << 3) + (lane & 7);
    const int b_csel = bg & 1;

    // prologue: B(0), B(1) into slots 0,1 + A(0) regs
    cp_async16(sbase + OFF_B + 0 * B_STG + boff, bsrc_h);
    cp_async16(sbase + OFF_B + 0 * B_STG + 4096 + boff, bsrc_l);
    asm volatile("cp.async.commit_group;");
    cp_async16(sbase + OFF_B + 1 * B_STG + boff, bsrc_h + KT);
    cp_async16(sbase + OFF_B + 1 * B_STG + 4096 + boff, bsrc_l + KT);
    asm volatile("cp.async.commit_group;");

    float4 areg[8];
#pragma unroll
    for (int i = 0; i < 8; ++i)
        areg[i] = ldcs4(Asrc + (size_t)(arow0 + 16 * i) * KFULL);

    float d[2][2][4] = {};

    for (int step = 0; step < NSTEPS; ++step) {
        const int abuf = step & 1;
        const uint32_t asm_base = sbase + abuf * 16384;

        // convert + STS A(step)
        {
            const int chunk = apos >> 1, half = apos & 1;
#pragma unroll
            for (int i = 0; i < 8; ++i) {
                const int row = arow0 + 16 * i;
                float4 f = areg[i];
                uint32_t h01, h23;
                asm("cvt.rn.f16x2.f32 %0, %1, %2;" : "=r"(h01) : "f"(f.y), "f"(f.x));
                asm("cvt.rn.f16x2.f32 %0, %1, %2;" : "=r"(h23) : "f"(f.w), "f"(f.z));
                const uint32_t off = row * 128 + ((chunk ^ (row & 7)) << 4) + half * 8;
                *(uint2*)(smem + abuf * 16384 + off) = make_uint2(h01, h23);
            }
        }

        // prefetch A(step+1) regs; issue B(step+2) into slot (step+2)&3
        if (step + 1 < NSTEPS) {
            const float* asrc2 = Asrc + (step + 1) * KT;
#pragma unroll
            for (int i = 0; i < 8; ++i)
                areg[i] = ldcs4(asrc2 + (size_t)(arow0 + 16 * i) * KFULL);
        }
        if (step + 2 < NSTEPS) {
            const uint32_t bslot = sbase + OFF_B + ((step + 2) & 3) * B_STG;
            cp_async16(bslot + boff, bsrc_h + (step + 2) * KT);
            cp_async16(bslot + 4096 + boff, bsrc_l + (step + 2) * KT);
        }
        asm volatile("cp.async.commit_group;");
        asm volatile("cp.async.wait_group 2;");
        __syncthreads();

        // compute: A[abuf], B slot step&3
        const uint32_t a_base0 = asm_base + a_row * 128;
        const uint32_t a_base1 = a_base0 + 16 * 128;
        const uint32_t bstg    = sbase + OFF_B + (step & 3) * B_STG + b_nrow * 128;
#pragma unroll
        for (int kt = 0; kt < 4; ++kt) {
            const int achunk = (2 * kt + a_csel) ^ (lane & 7);
            const int bchunk = (2 * kt + b_csel) ^ (lane & 7);
            uint32_t a0[4], a1[4], bh4[4], bl4[4];
            ldmatrix_x4(a0, a_base0 + (achunk << 4));
            ldmatrix_x4(a1, a_base1 + (achunk << 4));
            ldmatrix_x4(bh4, bstg + (bchunk << 4));
            ldmatrix_x4(bl4, bstg + 4096 + (bchunk << 4));
            mma16816(d[0][0], a0, bh4[0], bh4[1]);
            mma16816(d[0][0], a0, bl4[0], bl4[1]);
            mma16816(d[0][1], a0, bh4[2], bh4[3]);
            mma16816(d[0][1], a0, bl4[2], bl4[3]);
            mma16816(d[1][0], a1, bh4[0], bh4[1]);
            mma16816(d[1][0], a1, bl4[0], bl4[1]);
            mma16816(d[1][1], a1, bh4[2], bh4[3]);
            mma16816(d[1][1], a1, bl4[2], bl4[3]);
        }
    }

    // epilogue: fp16 partials. rows wr*32 + rt*16 + r4 (+8), cols wn*16 + nn*8 + kq
    const int r4 = lane >> 2, kq = (lane & 3) * 2;
    __half* po = g_part + ((size_t)blockIdx.y * NNODES + m0 + wr * 32 + r4) * DOUT
                        + wn * 16 + kq;
#pragma unroll
    for (int rt = 0; rt < 2; ++rt)
#pragma unroll
        for (int nn = 0; nn < 2; ++nn) {
            *(__half2*)(po + (size_t)(rt * 16)     * DOUT + nn * 8) =
                __floats2half2_rn(d[rt][nn][0], d[rt][nn][1]);
            *(__half2*)(po + (size_t)(rt * 16 + 8) * DOUT + nn * 8) =
                __floats2half2_rn(d[rt][nn][2], d[rt][nn][3]);
        }
}

// Stage 4: deterministic split-K reduction (fp16 partials -> fp32 out)
__global__ void k_reduce(float* __restrict__ out) {
    int i = blockIdx.x * blockDim.x + threadIdx.x;   // over 65536 half2s
    const __half2* p = (const __half2*)g_part;
    float2 s = __half22float2(p[i]);
#pragma unroll
    for (int sdx = 1; sdx < KSPLIT; ++sdx) {
        float2 v = __half22float2(p[(size_t)sdx * (NNODES * DOUT / 2) + i]);
        s.x += v.x; s.y += v.y;
    }
    ((float2*)out)[i] = s;
}

extern "C" void kernel_launch(void* const* d_in, const int* in_sizes, int n_in,
                              void* d_out, int out_size) {
    const float* X    = (const float*)d_in[0];   // [4096, 64]
    const float* A    = (const float*)d_in[1];   // [4096, 65536]
    const float* WF   = (const float*)d_in[2];   // [8, 64, 32]
    const float* comp = (const float*)d_in[3];   // [16, 8]
    float* out = (float*)d_out;                  // [4096, 32]

    cudaFuncSetAttribute((const void*)k_gemm,
                         cudaFuncAttributeMaxDynamicSharedMemorySize, SMEM_BYTES);

    k_fw<<<dim3(RREL, NNODES / 32), 256>>>(X, WF, comp);
    k_gemm<<<dim3(NNODES / M_TILE, KSPLIT), 256, SMEM_BYTES>>>(A);
    k_reduce<<<(NNODES * DOUT / 2) / 256, 256>>>(out);
}

// round 11
// speedup vs baseline: 1.0775x; 1.0722x over previous
#include <cuda_runtime.h>
#include <cuda_fp16.h>
#include <cstdint>

#define NNODES 4096
#define RREL   16
#define NBASES 8
#define DIN    64
#define DOUT   32
#define KFULL  (RREL * NNODES)          // 65536

#define M_TILE 128
#define KT     64                       // k per step (4 mma k-tiles of 16)
#define KSPLIT 64
#define KCHUNK (KFULL / KSPLIT)         // 1024
#define NSTEPS (KCHUNK / KT)            // 16

// gemm smem: A f16 tiles 2 x 16KB | B 4-slot ring, each slot BH 4K + BL 4K
#define OFF_B  32768
#define B_STG  8192
#define SMEM_BYTES (32768 + 4 * B_STG)  // 64 KB dynamic

#define XP 68                           // k_fw X smem pitch (floats)

__device__ __half g_Bh[(size_t)DOUT * KFULL];            // [c][k], 4 MB
__device__ __half g_Bl[(size_t)DOUT * KFULL];            // 4 MB
__device__ __half g_part[(size_t)KSPLIT * NNODES * DOUT]; // fp16 partials, 16 MB

__device__ __forceinline__ void mma16816(float* d, const uint32_t* a,
                                         uint32_t b0, uint32_t b1) {
    asm volatile(
        "mma.sync.aligned.m16n8k16.row.col.f32.f16.f16.f32 "
        "{%0,%1,%2,%3}, {%4,%5,%6,%7}, {%8,%9}, {%0,%1,%2,%3};"
        : "+f"(d[0]), "+f"(d[1]), "+f"(d[2]), "+f"(d[3])
        : "r"(a[0]), "r"(a[1]), "r"(a[2]), "r"(a[3]), "r"(b0), "r"(b1));
}
__device__ __forceinline__ void cp_async16(uint32_t saddr, const void* g) {
    asm volatile("cp.async.cg.shared.global [%0], [%1], 16;" :: "r"(saddr), "l"(g));
}
__device__ __forceinline__ void ldmatrix_x4(uint32_t* r, uint32_t addr) {
    asm volatile("ldmatrix.sync.aligned.m8n8.x4.shared.b16 {%0,%1,%2,%3}, [%4];"
                 : "=r"(r[0]), "=r"(r[1]), "=r"(r[2]), "=r"(r[3]) : "r"(addr));
}
// evict-first streaming load (A is single-use; keep B hot in L2)
__device__ __forceinline__ float4 ldcs4(const float* p) {
    float4 v;
    asm volatile("ld.global.cs.v4.f32 {%0,%1,%2,%3}, [%4];"
                 : "=f"(v.x), "=f"(v.y), "=f"(v.z), "=f"(v.w) : "l"(p));
    return v;
}

// Stage 1+2: W_r = comp[r] . WF, FW = X @ W_r -> fp16 hi/lo, transposed [c][k].
// Register-blocked 4x4 per thread; X rows spaced 32 apart => conflict-free LDS.
__global__ __launch_bounds__(256) void k_fw(const float* __restrict__ X,
                                            const float* __restrict__ WF,
                                            const float* __restrict__ comp) {
    __shared__ float Ws[DIN * DOUT];    // 8 KB
    __shared__ float Xs[128 * XP];      // 34.8 KB
    const int r = blockIdx.x, nblk = blockIdx.y, t = threadIdx.x;

    // W_r: 2048 entries, 8 per thread
#pragma unroll
    for (int j = 0; j < 8; ++j) {
        int ij = t + 256 * j;
        float s = 0.f;
#pragma unroll
        for (int b = 0; b < NBASES; ++b)
            s += comp[r * NBASES + b] * WF[b * (DIN * DOUT) + ij];
        Ws[ij] = s;
    }
    // X tile: 128 rows x 64, coalesced float4 loads
#pragma unroll
    for (int i = 0; i < 8; ++i) {
        int idx = t + 256 * i;              // 0..2047
        int row = idx >> 4, c4 = idx & 15;
        float4 v = *(const float4*)&X[(size_t)(nblk * 128 + row) * DIN + c4 * 4];
        *(float4*)&Xs[row * XP + c4 * 4] = v;
    }
    __syncthreads();

    const int rg = t >> 3;              // rows rg + 32*i
    const int cg = (t & 7) * 4;         // cols cg..cg+3
    float acc[4][4] = {};

#pragma unroll
    for (int k = 0; k < DIN; k += 4) {
        float4 w0 = *(const float4*)&Ws[(k + 0) * DOUT + cg];
        float4 w1 = *(const float4*)&Ws[(k + 1) * DOUT + cg];
        float4 w2 = *(const float4*)&Ws[(k + 2) * DOUT + cg];
        float4 w3 = *(const float4*)&Ws[(k + 3) * DOUT + cg];
#pragma unroll
        for (int i = 0; i < 4; ++i) {
            float4 x = *(const float4*)&Xs[(rg + 32 * i) * XP + k];
            acc[i][0] += x.x * w0.x + x.y * w1.x + x.z * w2.x + x.w * w3.x;
            acc[i][1] += x.x * w0.y + x.y * w1.y + x.z * w2.y + x.w * w3.y;
            acc[i][2] += x.x * w0.z + x.y * w1.z + x.z * w2.z + x.w * w3.z;
            acc[i][3] += x.x * w0.w + x.y * w1.w + x.z * w2.w + x.w * w3.w;
        }
    }

    const int kbase = r * NNODES + nblk * 128;
#pragma unroll
    for (int i = 0; i < 4; ++i)
#pragma unroll
        for (int j = 0; j < 4; ++j) {
            float v = acc[i][j];
            __half h = __float2half_rn(v);
            __half l = __float2half_rn(v - __half2float(h));
            size_t o = (size_t)(cg + j) * KFULL + kbase + rg + 32 * i;
            g_Bh[o] = h;
            g_Bl[o] = l;
        }
}

// Stage 3: split-K GEMM. Streaming LDG.cs -> in-reg fp16 convert -> swizzled
// smem (A 2-buf, B 4-slot cp.async ring) -> ldmatrix x4 -> 2-product mma.
__global__ __launch_bounds__(256, 2) void k_gemm(const float* __restrict__ A) {
    extern __shared__ char smem[];
    const uint32_t sbase = (uint32_t)__cvta_generic_to_shared(smem);

    const int t    = threadIdx.x;
    const int wid  = t >> 5, lane = t & 31;
    const int m0   = blockIdx.x * M_TILE;
    const size_t kb0 = (size_t)blockIdx.y * KCHUNK;

    const int wr = wid >> 1;
    const int wn = wid & 1;

    const int arow0 = t >> 4;
    const int apos  = t & 15;
    const float* Asrc = A + (size_t)m0 * KFULL + kb0 + apos * 4;

    const int bn = t >> 3, bkc = t & 7;
    const uint32_t boff = bn * 128 + ((bkc ^ (bn & 7)) << 4);
    const __half* bsrc_h = g_Bh + (size_t)bn * KFULL + kb0 + bkc * 8;
    const __half* bsrc_l = g_Bl + (size_t)bn * KFULL + kb0 + bkc * 8;

    const int a_row  = wr * 32 + (lane & 15);
    const int a_csel = lane >> 4;
    const int bg     = lane >> 3;
    const int b_nrow = wn * 16 + ((bg >> 1) << 3) + (lane & 7);
    const int b_csel = bg & 1;

    cp_async16(sbase + OFF_B + 0 * B_STG + boff, bsrc_h);
    cp_async16(sbase + OFF_B + 0 * B_STG + 4096 + boff, bsrc_l);
    asm volatile("cp.async.commit_group;");
    cp_async16(sbase + OFF_B + 1 * B_STG + boff, bsrc_h + KT);
    cp_async16(sbase + OFF_B + 1 * B_STG + 4096 + boff, bsrc_l + KT);
    asm volatile("cp.async.commit_group;");

    float4 areg[8];
#pragma unroll
    for (int i = 0; i < 8; ++i)
        areg[i] = ldcs4(Asrc + (size_t)(arow0 + 16 * i) * KFULL);

    float d[2][2][4] = {};

    for (int step = 0; step < NSTEPS; ++step) {
        const int abuf = step & 1;
        const uint32_t asm_base = sbase + abuf * 16384;

        {
            const int chunk = apos >> 1, half = apos & 1;
#pragma unroll
            for (int i = 0; i < 8; ++i) {
                const int row = arow0 + 16 * i;
                float4 f = areg[i];
                uint32_t h01, h23;
                asm("cvt.rn.f16x2.f32 %0, %1, %2;" : "=r"(h01) : "f"(f.y), "f"(f.x));
                asm("cvt.rn.f16x2.f32 %0, %1, %2;" : "=r"(h23) : "f"(f.w), "f"(f.z));
                const uint32_t off = row * 128 + ((chunk ^ (row & 7)) << 4) + half * 8;
                *(uint2*)(smem + abuf * 16384 + off) = make_uint2(h01, h23);
            }
        }

        if (step + 1 < NSTEPS) {
            const float* asrc2 = Asrc + (step + 1) * KT;
#pragma unroll
            for (int i = 0; i < 8; ++i)
                areg[i] = ldcs4(asrc2 + (size_t)(arow0 + 16 * i) * KFULL);
        }
        if (step + 2 < NSTEPS) {
            const uint32_t bslot = sbase + OFF_B + ((step + 2) & 3) * B_STG;
            cp_async16(bslot + boff, bsrc_h + (step + 2) * KT);
            cp_async16(bslot + 4096 + boff, bsrc_l + (step + 2) * KT);
        }
        asm volatile("cp.async.commit_group;");
        asm volatile("cp.async.wait_group 2;");
        __syncthreads();

        const uint32_t a_base0 = asm_base + a_row * 128;
        const uint32_t a_base1 = a_base0 + 16 * 128;
        const uint32_t bstg    = sbase + OFF_B + (step & 3) * B_STG + b_nrow * 128;
#pragma unroll
        for (int kt = 0; kt < 4; ++kt) {
            const int achunk = (2 * kt + a_csel) ^ (lane & 7);
            const int bchunk = (2 * kt + b_csel) ^ (lane & 7);
            uint32_t a0[4], a1[4], bh4[4], bl4[4];
            ldmatrix_x4(a0, a_base0 + (achunk << 4));
            ldmatrix_x4(a1, a_base1 + (achunk << 4));
            ldmatrix_x4(bh4, bstg + (bchunk << 4));
            ldmatrix_x4(bl4, bstg + 4096 + (bchunk << 4));
            mma16816(d[0][0], a0, bh4[0], bh4[1]);
            mma16816(d[0][0], a0, bl4[0], bl4[1]);
            mma16816(d[0][1], a0, bh4[2], bh4[3]);
            mma16816(d[0][1], a0, bl4[2], bl4[3]);
            mma16816(d[1][0], a1, bh4[0], bh4[1]);
            mma16816(d[1][0], a1, bl4[0], bl4[1]);
            mma16816(d[1][1], a1, bh4[2], bh4[3]);
            mma16816(d[1][1], a1, bl4[2], bl4[3]);
        }
    }

    // epilogue: fp16 partials
    const int r4 = lane >> 2, kq = (lane & 3) * 2;
    __half* po = g_part + ((size_t)blockIdx.y * NNODES + m0 + wr * 32 + r4) * DOUT
                        + wn * 16 + kq;
#pragma unroll
    for (int rt = 0; rt < 2; ++rt)
#pragma unroll
        for (int nn = 0; nn < 2; ++nn) {
            *(__half2*)(po + (size_t)(rt * 16)     * DOUT + nn * 8) =
                __floats2half2_rn(d[rt][nn][0], d[rt][nn][1]);
            *(__half2*)(po + (size_t)(rt * 16 + 8) * DOUT + nn * 8) =
                __floats2half2_rn(d[rt][nn][2], d[rt][nn][3]);
        }
}

// Stage 4: deterministic split-K reduction (fp16 partials -> fp32 out)
__global__ void k_reduce(float* __restrict__ out) {
    int i = blockIdx.x * blockDim.x + threadIdx.x;   // over 65536 half2s
    const __half2* p = (const __half2*)g_part;
    float2 s = __half22float2(p[i]);
#pragma unroll
    for (int sdx = 1; sdx < KSPLIT; ++sdx) {
        float2 v = __half22float2(p[(size_t)sdx * (NNODES * DOUT / 2) + i]);
        s.x += v.x; s.y += v.y;
    }
    ((float2*)out)[i] = s;
}

extern "C" void kernel_launch(void* const* d_in, const int* in_sizes, int n_in,
                              void* d_out, int out_size) {
    const float* X    = (const float*)d_in[0];   // [4096, 64]
    const float* A    = (const float*)d_in[1];   // [4096, 65536]
    const float* WF   = (const float*)d_in[2];   // [8, 64, 32]
    const float* comp = (const float*)d_in[3];   // [16, 8]
    float* out = (float*)d_out;                  // [4096, 32]

    cudaFuncSetAttribute((const void*)k_gemm,
                         cudaFuncAttributeMaxDynamicSharedMemorySize, SMEM_BYTES);

    k_fw<<<dim3(RREL, NNODES / 128), 256>>>(X, WF, comp);
    k_gemm<<<dim3(NNODES / M_TILE, KSPLIT), 256, SMEM_BYTES>>>(A);
    k_reduce<<<(NNODES * DOUT / 2) / 256, 256>>>(out);
}

// round 12
// speedup vs baseline: 1.0815x; 1.0037x over previous
#include <cuda_runtime.h>
#include <cuda_fp16.h>
#include <cstdint>

#define NNODES 4096
#define RREL   16
#define NBASES 8
#define DIN    64
#define DOUT   32
#define KFULL  (RREL * NNODES)          // 65536

#define M_TILE 128
#define KT     64                       // k per step (4 mma k-tiles of 16)
#define KSPLIT 64
#define KCHUNK (KFULL / KSPLIT)         // 1024
#define NSTEPS (KCHUNK / KT)            // 16

// gemm smem: A f16 tiles 2 x 16KB | B 4-slot ring, each slot BH 4K + BL 4K
#define OFF_B  32768
#define B_STG  8192
#define SMEM_BYTES (32768 + 4 * B_STG)  // 64 KB dynamic

#define XP 68                           // k_fw X smem pitch (floats)

__device__ __half g_Bh[(size_t)DOUT * KFULL];            // [c][k], 4 MB
__device__ __half g_Bl[(size_t)DOUT * KFULL];            // 4 MB
__device__ __half g_part[(size_t)KSPLIT * NNODES * DOUT]; // fp16 partials, 16 MB

__device__ __forceinline__ void mma16816(float* d, const uint32_t* a,
                                         uint32_t b0, uint32_t b1) {
    asm volatile(
        "mma.sync.aligned.m16n8k16.row.col.f32.f16.f16.f32 "
        "{%0,%1,%2,%3}, {%4,%5,%6,%7}, {%8,%9}, {%0,%1,%2,%3};"
        : "+f"(d[0]), "+f"(d[1]), "+f"(d[2]), "+f"(d[3])
        : "r"(a[0]), "r"(a[1]), "r"(a[2]), "r"(a[3]), "r"(b0), "r"(b1));
}
__device__ __forceinline__ void cp_async16(uint32_t saddr, const void* g) {
    asm volatile("cp.async.cg.shared.global [%0], [%1], 16;" :: "r"(saddr), "l"(g));
}
__device__ __forceinline__ void ldmatrix_x4(uint32_t* r, uint32_t addr) {
    asm volatile("ldmatrix.sync.aligned.m8n8.x4.shared.b16 {%0,%1,%2,%3}, [%4];"
                 : "=r"(r[0]), "=r"(r[1]), "=r"(r[2]), "=r"(r[3]) : "r"(addr));
}
// evict-first streaming load (A is single-use; keep B hot in L2)
__device__ __forceinline__ float4 ldcs4(const float* p) {
    float4 v;
    asm volatile("ld.global.cs.v4.f32 {%0,%1,%2,%3}, [%4];"
                 : "=f"(v.x), "=f"(v.y), "=f"(v.z), "=f"(v.w) : "l"(p));
    return v;
}

// Stage 1+2: W_r = comp[r] . WF, FW = X @ W_r -> fp16 hi/lo, transposed [c][k].
// Register-blocked 4x4 per thread; X rows spaced 32 apart => conflict-free LDS.
__global__ __launch_bounds__(256) void k_fw(const float* __restrict__ X,
                                            const float* __restrict__ WF,
                                            const float* __restrict__ comp) {
    __shared__ float Ws[DIN * DOUT];    // 8 KB
    __shared__ float Xs[128 * XP];      // 34.8 KB
    const int r = blockIdx.x, nblk = blockIdx.y, t = threadIdx.x;

    // W_r: 2048 entries, 8 per thread
#pragma unroll
    for (int j = 0; j < 8; ++j) {
        int ij = t + 256 * j;
        float s = 0.f;
#pragma unroll
        for (int b = 0; b < NBASES; ++b)
            s += comp[r * NBASES + b] * WF[b * (DIN * DOUT) + ij];
        Ws[ij] = s;
    }
    // X tile: 128 rows x 64, coalesced float4 loads
#pragma unroll
    for (int i = 0; i < 8; ++i) {
        int idx = t + 256 * i;              // 0..2047
        int row = idx >> 4, c4 = idx & 15;
        float4 v = *(const float4*)&X[(size_t)(nblk * 128 + row) * DIN + c4 * 4];
        *(float4*)&Xs[row * XP + c4 * 4] = v;
    }
    __syncthreads();

    const int rg = t >> 3;              // rows rg + 32*i
    const int cg = (t & 7) * 4;         // cols cg..cg+3
    float acc[4][4] = {};

#pragma unroll
    for (int k = 0; k < DIN; k += 4) {
        float4 w0 = *(const float4*)&Ws[(k + 0) * DOUT + cg];
        float4 w1 = *(const float4*)&Ws[(k + 1) * DOUT + cg];
        float4 w2 = *(const float4*)&Ws[(k + 2) * DOUT + cg];
        float4 w3 = *(const float4*)&Ws[(k + 3) * DOUT + cg];
#pragma unroll
        for (int i = 0; i < 4; ++i) {
            float4 x = *(const float4*)&Xs[(rg + 32 * i) * XP + k];
            acc[i][0] += x.x * w0.x + x.y * w1.x + x.z * w2.x + x.w * w3.x;
            acc[i][1] += x.x * w0.y + x.y * w1.y + x.z * w2.y + x.w * w3.y;
            acc[i][2] += x.x * w0.z + x.y * w1.z + x.z * w2.z + x.w * w3.z;
            acc[i][3] += x.x * w0.w + x.y * w1.w + x.z * w2.w + x.w * w3.w;
        }
    }

    const int kbase = r * NNODES + nblk * 128;
#pragma unroll
    for (int i = 0; i < 4; ++i)
#pragma unroll
        for (int j = 0; j < 4; ++j) {
            float v = acc[i][j];
            __half h = __float2half_rn(v);
            __half l = __float2half_rn(v - __half2float(h));
            size_t o = (size_t)(cg + j) * KFULL + kbase + rg + 32 * i;
            g_Bh[o] = h;
            g_Bl[o] = l;
        }
}

// Stage 3: split-K GEMM. Streaming LDG.cs -> in-reg fp16 convert -> swizzled
// smem (A 2-buf, B 4-slot cp.async ring) -> ldmatrix x4 -> 2-product mma.
__global__ __launch_bounds__(256, 2) void k_gemm(const float* __restrict__ A) {
    extern __shared__ char smem[];
    const uint32_t sbase = (uint32_t)__cvta_generic_to_shared(smem);

    const int t    = threadIdx.x;
    const int wid  = t >> 5, lane = t & 31;
    const int m0   = blockIdx.x * M_TILE;
    const size_t kb0 = (size_t)blockIdx.y * KCHUNK;

    const int wr = wid >> 1;
    const int wn = wid & 1;

    const int arow0 = t >> 4;
    const int apos  = t & 15;
    const float* Asrc = A + (size_t)m0 * KFULL + kb0 + apos * 4;

    const int bn = t >> 3, bkc = t & 7;
    const uint32_t boff = bn * 128 + ((bkc ^ (bn & 7)) << 4);
    const __half* bsrc_h = g_Bh + (size_t)bn * KFULL + kb0 + bkc * 8;
    const __half* bsrc_l = g_Bl + (size_t)bn * KFULL + kb0 + bkc * 8;

    const int a_row  = wr * 32 + (lane & 15);
    const int a_csel = lane >> 4;
    const int bg     = lane >> 3;
    const int b_nrow = wn * 16 + ((bg >> 1) << 3) + (lane & 7);
    const int b_csel = bg & 1;

    cp_async16(sbase + OFF_B + 0 * B_STG + boff, bsrc_h);
    cp_async16(sbase + OFF_B + 0 * B_STG + 4096 + boff, bsrc_l);
    asm volatile("cp.async.commit_group;");
    cp_async16(sbase + OFF_B + 1 * B_STG + boff, bsrc_h + KT);
    cp_async16(sbase + OFF_B + 1 * B_STG + 4096 + boff, bsrc_l + KT);
    asm volatile("cp.async.commit_group;");

    float4 areg[8];
#pragma unroll
    for (int i = 0; i < 8; ++i)
        areg[i] = ldcs4(Asrc + (size_t)(arow0 + 16 * i) * KFULL);

    float d[2][2][4] = {};

    for (int step = 0; step < NSTEPS; ++step) {
        const int abuf = step & 1;
        const uint32_t asm_base = sbase + abuf * 16384;

        {
            const int chunk = apos >> 1, half = apos & 1;
#pragma unroll
            for (int i = 0; i < 8; ++i) {
                const int row = arow0 + 16 * i;
                float4 f = areg[i];
                uint32_t h01, h23;
                asm("cvt.rn.f16x2.f32 %0, %1, %2;" : "=r"(h01) : "f"(f.y), "f"(f.x));
                asm("cvt.rn.f16x2.f32 %0, %1, %2;" : "=r"(h23) : "f"(f.w), "f"(f.z));
                const uint32_t off = row * 128 + ((chunk ^ (row & 7)) << 4) + half * 8;
                *(uint2*)(smem + abuf * 16384 + off) = make_uint2(h01, h23);
            }
        }

        if (step + 1 < NSTEPS) {
            const float* asrc2 = Asrc + (step + 1) * KT;
#pragma unroll
            for (int i = 0; i < 8; ++i)
                areg[i] = ldcs4(asrc2 + (size_t)(arow0 + 16 * i) * KFULL);
        }
        if (step + 2 < NSTEPS) {
            const uint32_t bslot = sbase + OFF_B + ((step + 2) & 3) * B_STG;
            cp_async16(bslot + boff, bsrc_h + (step + 2) * KT);
            cp_async16(bslot + 4096 + boff, bsrc_l + (step + 2) * KT);
        }
        asm volatile("cp.async.commit_group;");
        asm volatile("cp.async.wait_group 2;");
        __syncthreads();

        const uint32_t a_base0 = asm_base + a_row * 128;
        const uint32_t a_base1 = a_base0 + 16 * 128;
        const uint32_t bstg    = sbase + OFF_B + (step & 3) * B_STG + b_nrow * 128;
#pragma unroll
        for (int kt = 0; kt < 4; ++kt) {
            const int achunk = (2 * kt + a_csel) ^ (lane & 7);
            const int bchunk = (2 * kt + b_csel) ^ (lane & 7);
            uint32_t a0[4], a1[4], bh4[4], bl4[4];
            ldmatrix_x4(a0, a_base0 + (achunk << 4));
            ldmatrix_x4(a1, a_base1 + (achunk << 4));
            ldmatrix_x4(bh4, bstg + (bchunk << 4));
            ldmatrix_x4(bl4, bstg + 4096 + (bchunk << 4));
            mma16816(d[0][0], a0, bh4[0], bh4[1]);
            mma16816(d[0][0], a0, bl4[0], bl4[1]);
            mma16816(d[0][1], a0, bh4[2], bh4[3]);
            mma16816(d[0][1], a0, bl4[2], bl4[3]);
            mma16816(d[1][0], a1, bh4[0], bh4[1]);
            mma16816(d[1][0], a1, bl4[0], bl4[1]);
            mma16816(d[1][1], a1, bh4[2], bh4[3]);
            mma16816(d[1][1], a1, bl4[2], bl4[3]);
        }
    }

    // epilogue: fp16 partials
    const int r4 = lane >> 2, kq = (lane & 3) * 2;
    __half* po = g_part + ((size_t)blockIdx.y * NNODES + m0 + wr * 32 + r4) * DOUT
                        + wn * 16 + kq;
#pragma unroll
    for (int rt = 0; rt < 2; ++rt)
#pragma unroll
        for (int nn = 0; nn < 2; ++nn) {
            *(__half2*)(po + (size_t)(rt * 16)     * DOUT + nn * 8) =
                __floats2half2_rn(d[rt][nn][0], d[rt][nn][1]);
            *(__half2*)(po + (size_t)(rt * 16 + 8) * DOUT + nn * 8) =
                __floats2half2_rn(d[rt][nn][2], d[rt][nn][3]);
        }
}

// Stage 4: deterministic split-K reduction (fp16 partials -> fp32 out)
__global__ void k_reduce(float* __restrict__ out) {
    int i = blockIdx.x * blockDim.x + threadIdx.x;   // over 65536 half2s
    const __half2* p = (const __half2*)g_part;
    float2 s = __half22float2(p[i]);
#pragma unroll
    for (int sdx = 1; sdx < KSPLIT; ++sdx) {
        float2 v = __half22float2(p[(size_t)sdx * (NNODES * DOUT / 2) + i]);
        s.x += v.x; s.y += v.y;
    }
    ((float2*)out)[i] = s;
}

extern "C" void kernel_launch(void* const* d_in, const int* in_sizes, int n_in,
                              void* d_out, int out_size) {
    const float* X    = (const float*)d_in[0];   // [4096, 64]
    const float* A    = (const float*)d_in[1];   // [4096, 65536]
    const float* WF   = (const float*)d_in[2];   // [8, 64, 32]
    const float* comp = (const float*)d_in[3];   // [16, 8]
    float* out = (float*)d_out;                  // [4096, 32]

    cudaFuncSetAttribute((const void*)k_gemm,
                         cudaFuncAttributeMaxDynamicSharedMemorySize, SMEM_BYTES);

    k_fw<<<dim3(RREL, NNODES / 128), 256>>>(X, WF, comp);
    k_gemm<<<dim3(NNODES / M_TILE, KSPLIT), 256, SMEM_BYTES>>>(A);
    k_reduce<<<(NNODES * DOUT / 2) / 256, 256>>>(out);
}